// round 13
// baseline (speedup 1.0000x reference)
#include <cuda_runtime.h>
#include <math.h>
#include <stdint.h>

#define LF 104          // node feature length
#define SS 500          // sink outputs / classes
#define MM 64           // molecules
#define TT 32           // topological levels
#define WW 256          // nodes per level
#define NROWS (MM*WW)   // 16384
#define RT 128          // rows per CTA
#define NTHR 832        // 26 warps: warp w = cols 4w..4w+3, lane l = rows 4l..4l+3
#define KC 16           // K chunk
#define SEGC 7          // chunks per segment (104 padded to 112)

__device__ float g_hA[NROWS*LF];
__device__ float g_hB[NROWS*LF];
__device__ float g_sink[MM*SS];

typedef unsigned long long u64;

__device__ __forceinline__ u64 dup2(float x){
    u64 r; asm("mov.b64 %0, {%1, %1};" : "=l"(r) : "f"(x)); return r;
}
__device__ __forceinline__ void fma2(u64 &d, u64 a, u64 b){
    asm("fma.rn.f32x2 %0, %1, %2, %0;" : "+l"(d) : "l"(a), "l"(b));
}
__device__ __forceinline__ float2 unpack2(u64 a){
    float2 v; asm("mov.b64 {%0, %1}, %2;" : "=f"(v.x), "=f"(v.y) : "l"(a)); return v;
}

// Unified level kernel.
//  t == 0: nchunk = 7,  Wm = W_single [104,104], input = context[:,0]
//  t >= 1: nchunk = 21, Wm = W_int2  [312,104], input = [ctx | par0 | par1]
// chunk c: seg = c/7 (0 ctx, 1 parent0, 2 parent1), k_in_seg base = (c%7)*16,
// k_in_seg >= 104 is zero-padded (weights and inputs).
__global__ void __launch_bounds__(NTHR, 1) level_kernel(
    const float* __restrict__ ctx, const int* __restrict__ pidx,
    const float* __restrict__ Wm, const float* __restrict__ bias,
    int t, int nchunk)
{
    __shared__ u64   sWd[2][KC*LF];   // 26624 B: duplicated weights [buf][k*LF + col]
    __shared__ float sIn[2][KC*RT];   // 16384 B: inputs [buf][k*RT + r]

    const float* hsrc = (t & 1) ? g_hA : g_hB;
    float*       hdst = (t & 1) ? g_hB : g_hA;

    const int tid = threadIdx.x;
    const int wid = tid >> 5;          // 0..25 -> cols 4*wid..4*wid+3
    const int lane = tid & 31;         // rows 4*lane..4*lane+3
    const int rbase = blockIdx.x * RT;

    u64 acc[2][4];                     // [rowpair][col]; lanes = (even row, odd row)
    #pragma unroll
    for (int i = 0; i < 2; ++i)
        #pragma unroll
        for (int j = 0; j < 4; ++j) acc[i][j] = 0ULL;

    const int wvalid = tid < 416;      // weight stagers: 16 kr x 26 cq
    const int ivalid = tid < 512;      // input stagers:  4 q x 128 r
    const int s_kr = tid / 26, s_cq = tid % 26;      // weight role
    const int s_r  = tid & 127, s_q = tid >> 7;      // input role
    const int s_m  = (rbase + s_r) >> 8;
    const int s_w  = (rbase + s_r) & 255;

    float4 wpre = make_float4(0.f,0.f,0.f,0.f);
    float4 ipre = wpre;

    // ---- LDG chunk c into registers ----
    auto load_chunk = [&](int c) {
        const int seg = c / SEGC;
        const int kseg0 = (c % SEGC) * KC;
        if (wvalid) {
            int kk = kseg0 + s_kr;
            wpre = (kk < LF) ? *(const float4*)&Wm[(size_t)(seg*LF + kk)*LF + s_cq*4]
                             : make_float4(0.f,0.f,0.f,0.f);
        }
        if (ivalid) {
            int kk = kseg0 + s_q*4;
            if (kk >= LF) {
                ipre = make_float4(0.f,0.f,0.f,0.f);
            } else if (seg == 0) {
                ipre = *(const float4*)&ctx[(((size_t)s_m*TT + t)*WW + s_w)*LF + kk];
            } else {
                int p = pidx[(((size_t)s_m*(TT-1) + (t-1))*WW + s_w)*2 + (seg-1)];
                ipre = *(const float4*)&hsrc[((size_t)s_m*WW + p)*LF + kk];
            }
        }
    };
    // ---- registers -> smem buffer b ----
    auto store_chunk = [&](int b) {
        if (wvalid) {
            u64* d = &sWd[b][s_kr*LF + s_cq*4];
            ulonglong2 w01; w01.x = dup2(wpre.x); w01.y = dup2(wpre.y);
            ulonglong2 w23; w23.x = dup2(wpre.z); w23.y = dup2(wpre.w);
            *(ulonglong2*)(d)     = w01;
            *(ulonglong2*)(d + 2) = w23;
        }
        if (ivalid) {
            sIn[b][(s_q*4    )*RT + s_r] = ipre.x;
            sIn[b][(s_q*4 + 1)*RT + s_r] = ipre.y;
            sIn[b][(s_q*4 + 2)*RT + s_r] = ipre.z;
            sIn[b][(s_q*4 + 3)*RT + s_r] = ipre.w;
        }
    };

    load_chunk(0);
    store_chunk(0);
    __syncthreads();

    for (int c = 0; c < nchunk; ++c) {
        if (c + 1 < nchunk) load_chunk(c + 1);   // LDG hidden under compute

        const int b = c & 1;
        const u64*   wb = &sWd[b][4*wid];
        const float* ib = &sIn[b][4*lane];
        #pragma unroll
        for (int k = 0; k < KC; ++k) {
            ulonglong2 av  = *(const ulonglong2*)(ib + k*RT);      // rows 4l..4l+3
            ulonglong2 w01 = *(const ulonglong2*)(wb + k*LF);      // cols 4w,4w+1 (bcast)
            ulonglong2 w23 = *(const ulonglong2*)(wb + k*LF + 2);  // cols 4w+2,4w+3
            fma2(acc[0][0], av.x, w01.x); fma2(acc[0][1], av.x, w01.y);
            fma2(acc[0][2], av.x, w23.x); fma2(acc[0][3], av.x, w23.y);
            fma2(acc[1][0], av.y, w01.x); fma2(acc[1][1], av.y, w01.y);
            fma2(acc[1][2], av.y, w23.x); fma2(acc[1][3], av.y, w23.y);
        }

        if (c + 1 < nchunk) store_chunk((c + 1) & 1);  // other buffer: no pre-sync needed
        __syncthreads();
    }

    // ---- epilogue: + bias, ReLU, store fp32 ----
    {
        float4 bv = *(const float4*)&bias[4*wid];
        #pragma unroll
        for (int rp = 0; rp < 2; ++rp) {
            float2 v0 = unpack2(acc[rp][0]);
            float2 v1 = unpack2(acc[rp][1]);
            float2 v2 = unpack2(acc[rp][2]);
            float2 v3 = unpack2(acc[rp][3]);
            size_t r0 = (size_t)rbase + 4*lane + 2*rp;
            float4 oe = make_float4(fmaxf(v0.x + bv.x, 0.f), fmaxf(v1.x + bv.y, 0.f),
                                    fmaxf(v2.x + bv.z, 0.f), fmaxf(v3.x + bv.w, 0.f));
            float4 oo = make_float4(fmaxf(v0.y + bv.x, 0.f), fmaxf(v1.y + bv.y, 0.f),
                                    fmaxf(v2.y + bv.z, 0.f), fmaxf(v3.y + bv.w, 0.f));
            *(float4*)&hdst[r0*LF + 4*wid]       = oe;
            *(float4*)&hdst[(r0 + 1)*LF + 4*wid] = oo;
        }
    }
}

// -------- sink: sink_out[m,s] = concat7(h_last) . W_sink7[:,s] --------
__global__ void __launch_bounds__(128) sink_kernel(
    const int* __restrict__ sidx, const float* __restrict__ Wk)
{
    __shared__ float sh[7*LF];
    const int m = blockIdx.x;
    const int tid = threadIdx.x;
    const float* h = g_hB;   // level 31 output (31 odd)

    for (int idx = tid; idx < 7*LF; idx += 128) {
        int j = idx / LF, l = idx % LF;
        int p = sidx[m*7 + j];
        sh[idx] = h[((size_t)m*WW + p)*LF + l];
    }
    __syncthreads();

    int s = blockIdx.y * 128 + tid;
    if (s < SS) {
        float acc = 0.f;
        #pragma unroll 8
        for (int kk = 0; kk < 7*LF; ++kk)
            acc = fmaf(sh[kk], Wk[(size_t)kk*SS + s], acc);
        g_sink[(size_t)m*SS + s] = acc;
    }
}

// -------- final: mean over M + b_sink7, 500x500 matvec + b_cls, sigmoid --------
__global__ void __launch_bounds__(512) final_kernel(
    const float* __restrict__ bs, const float* __restrict__ Wc,
    const float* __restrict__ bc, float* __restrict__ out)
{
    __shared__ float avg[SS];
    const int tid = threadIdx.x;
    for (int s = tid; s < SS; s += 512) {
        float a = 0.f;
        #pragma unroll 8
        for (int m = 0; m < MM; ++m) a += g_sink[(size_t)m*SS + s];
        avg[s] = a * (1.0f/MM) + bs[s];
    }
    __syncthreads();
    for (int s = tid; s < SS; s += 512) {
        float acc = bc[s];
        #pragma unroll 4
        for (int i = 0; i < SS; ++i)
            acc = fmaf(avg[i], Wc[(size_t)i*SS + s], acc);
        out[s] = 1.0f / (1.0f + expf(-acc));
    }
}

extern "C" void kernel_launch(void* const* d_in, const int* in_sizes, int n_in,
                              void* d_out, int out_size)
{
    const float* ctx      = (const float*)d_in[0];
    const int*   pidx     = (const int*)  d_in[1];
    const int*   sidx     = (const int*)  d_in[2];
    const float* W_single = (const float*)d_in[3];
    const float* b_single = (const float*)d_in[4];
    const float* W_int2   = (const float*)d_in[5];
    const float* b_int2   = (const float*)d_in[6];
    const float* W_sink7  = (const float*)d_in[7];
    const float* b_sink7  = (const float*)d_in[8];
    const float* W_cls    = (const float*)d_in[9];
    const float* b_cls    = (const float*)d_in[10];
    float* out = (float*)d_out;

    dim3 grid(NROWS / RT);   // 128 CTAs, 1 per SM

    level_kernel<<<grid, NTHR>>>(ctx, pidx, W_single, b_single, 0, SEGC);
    for (int t = 1; t < TT; ++t)
        level_kernel<<<grid, NTHR>>>(ctx, pidx, W_int2, b_int2, t, 3*SEGC);

    sink_kernel<<<dim3(MM, (SS + 127)/128), 128>>>(sidx, W_sink7);
    final_kernel<<<1, 512>>>(b_sink7, W_cls, b_cls, out);
}